// round 2
// baseline (speedup 1.0000x reference)
#include <cuda_runtime.h>
#include <math.h>

#define EPSF 1e-3f

// ---- scratch (allocation-free: __device__ globals) ----
// A: [4096][12544] im2col, k-index = bin*256 + c
__device__ float g_A[4096UL * 12544UL];
// w1 permuted to [512][bin*256 + c]
__device__ float g_W1p[512UL * 12544UL];
__device__ float g_H1[4096UL * 512UL];
__device__ float g_H2[4096UL * 512UL];

// ------------------------------------------------------------------
// Permute w1 [O=512, C=256, 7, 7] (k = c*49 + bin) -> [O, bin*256 + c]
// Output-coalesced; input reads strided (small tensor, cheap).
// ------------------------------------------------------------------
__global__ void permute_w1_kernel(const float* __restrict__ w1) {
    int i = blockIdx.x * 256 + threadIdx.x;   // 512*12544 = 6422528 exactly
    int o = i / 12544;
    int k = i - o * 12544;
    int c   = k & 255;
    int bin = k >> 8;
    g_W1p[i] = w1[o * 12544 + c * 49 + bin];
}

// ------------------------------------------------------------------
// RoIAlign + im2col. One block per roi (4096), thread = channel (256).
// Writes A[r][bin*256 + c]  -> fully coalesced along c.
// ------------------------------------------------------------------
__global__ void roi_im2col_kernel(const float* __restrict__ images,
                                  const int*   __restrict__ kfi,
                                  const float* __restrict__ boxes) {
    const int r = blockIdx.x;     // 0..4095
    const int c = threadIdx.x;    // 0..255

    const int f = kfi[r];
    const float x1 = boxes[r * 4 + 0] * 40.0f;
    const float y1 = boxes[r * 4 + 1] * 40.0f;
    const float x2 = boxes[r * 4 + 2] * 40.0f;
    const float y2 = boxes[r * 4 + 3] * 40.0f;
    const float bw = (x2 - x1) / 7.0f;
    const float bh = (y2 - y1) / 7.0f;

    const float* __restrict__ img = images + (size_t)f * 256 * 1600 + (size_t)c * 1600;
    float* __restrict__ arow = g_A + (size_t)r * 12544 + c;

    #pragma unroll 7
    for (int bin = 0; bin < 49; ++bin) {
        const int by = bin / 7;
        const int bx = bin - by * 7;
        const float X = x1 + ((float)bx + 0.5f) * bw;
        const float Y = y1 + ((float)by + 0.5f) * bh;
        const bool valid = (X > -1.0f) && (X < 40.0f) && (Y > -1.0f) && (Y < 40.0f);

        float x = fminf(fmaxf(X, 0.0f), 39.0f);
        float y = fminf(fmaxf(Y, 0.0f), 39.0f);
        const int x0 = (int)floorf(x);
        const int y0 = (int)floorf(y);
        const int x1i = min(x0 + 1, 39);
        const int y1i = min(y0 + 1, 39);
        const float lx = x - (float)x0;
        const float ly = y - (float)y0;
        const float w00 = (1.0f - ly) * (1.0f - lx);
        const float w01 = (1.0f - ly) * lx;
        const float w10 = ly * (1.0f - lx);
        const float w11 = ly * lx;

        float v = 0.0f;
        if (valid) {
            v = img[y0  * 40 + x0 ] * w00
              + img[y0  * 40 + x1i] * w01
              + img[y1i * 40 + x0 ] * w10
              + img[y1i * 40 + x1i] * w11;
        }
        arow[bin * 256] = v;
    }
}

// ------------------------------------------------------------------
// NT SGEMM: C[M,N] = A[M,K] * B[N,K]^T with fused bias + BN + ReLU.
// BM=BN=128, BK=8, 256 threads, 8x8 microtiles. ldc = 512 (both uses).
// ------------------------------------------------------------------
#define BM 128
#define BN 128
#define BKT 8

__global__ __launch_bounds__(256) void gemm_bn_relu_kernel(
    const float* __restrict__ A, const float* __restrict__ B,
    float* __restrict__ C, int K,
    const float* __restrict__ bias,
    const float* __restrict__ gamma, const float* __restrict__ beta,
    const float* __restrict__ mean,  const float* __restrict__ var) {

    __shared__ float As[BKT][BM];
    __shared__ float Bs[BKT][BN];

    const int t  = threadIdx.x;
    const int bm = blockIdx.x * BM;
    const int bn = blockIdx.y * BN;

    const int lr = t >> 1;          // 0..127 : row within tile
    const int lk = (t & 1) * 4;     // 0 or 4 : k-offset (float4)
    const float* Ab = A + (size_t)(bm + lr) * K + lk;
    const float* Bb = B + (size_t)(bn + lr) * K + lk;

    const int tx = t & 15;          // col group
    const int ty = t >> 4;          // row group

    float acc[8][8];
    #pragma unroll
    for (int i = 0; i < 8; ++i)
        #pragma unroll
        for (int j = 0; j < 8; ++j) acc[i][j] = 0.0f;

    for (int k0 = 0; k0 < K; k0 += BKT) {
        const float4 av = *(const float4*)(Ab + k0);
        const float4 bv = *(const float4*)(Bb + k0);
        __syncthreads();
        As[lk + 0][lr] = av.x; As[lk + 1][lr] = av.y;
        As[lk + 2][lr] = av.z; As[lk + 3][lr] = av.w;
        Bs[lk + 0][lr] = bv.x; Bs[lk + 1][lr] = bv.y;
        Bs[lk + 2][lr] = bv.z; Bs[lk + 3][lr] = bv.w;
        __syncthreads();

        #pragma unroll
        for (int kk = 0; kk < BKT; ++kk) {
            float a[8], b[8];
            *(float4*)&a[0] = *(const float4*)&As[kk][ty * 8];
            *(float4*)&a[4] = *(const float4*)&As[kk][ty * 8 + 4];
            *(float4*)&b[0] = *(const float4*)&Bs[kk][tx * 8];
            *(float4*)&b[4] = *(const float4*)&Bs[kk][tx * 8 + 4];
            #pragma unroll
            for (int i = 0; i < 8; ++i)
                #pragma unroll
                for (int j = 0; j < 8; ++j)
                    acc[i][j] = fmaf(a[i], b[j], acc[i][j]);
        }
    }

    // epilogue: relu( (acc + bias - mean) * gamma*rsqrt(var+eps) + beta )
    #pragma unroll
    for (int j = 0; j < 8; ++j) {
        const int col = bn + tx * 8 + j;
        const float s   = gamma[col] * rsqrtf(var[col] + EPSF);
        const float off = (bias[col] - mean[col]) * s + beta[col];
        #pragma unroll
        for (int i = 0; i < 8; ++i) {
            const int row = bm + ty * 8 + i;
            const float v = fmaxf(acc[i][j] * s + off, 0.0f);
            C[(size_t)row * 512 + col] = v;
        }
    }
}

// ------------------------------------------------------------------
// max over K=8 keyframes: out[n][d] = max_k H2[n*8+k][d]
// ------------------------------------------------------------------
__global__ void max_k_kernel(const float* __restrict__ H2, float* __restrict__ out) {
    const int n = blockIdx.x;   // 0..511
    const int d = threadIdx.x;  // 0..511
    const float* p = H2 + (size_t)n * 8 * 512 + d;
    float m = p[0];
    #pragma unroll
    for (int k = 1; k < 8; ++k) m = fmaxf(m, p[(size_t)k * 512]);
    out[(size_t)n * 512 + d] = m;
}

// ------------------------------------------------------------------
extern "C" void kernel_launch(void* const* d_in, const int* in_sizes, int n_in,
                              void* d_out, int out_size) {
    const float* images = (const float*)d_in[0];
    const int*   kfi    = (const int*)  d_in[1];
    const float* boxes  = (const float*)d_in[2];
    const float* w1     = (const float*)d_in[3];
    const float* b1     = (const float*)d_in[4];
    const float* g1     = (const float*)d_in[5];
    const float* bt1    = (const float*)d_in[6];
    const float* m1     = (const float*)d_in[7];
    const float* v1     = (const float*)d_in[8];
    const float* w2     = (const float*)d_in[9];
    const float* b2     = (const float*)d_in[10];
    const float* g2     = (const float*)d_in[11];
    const float* bt2    = (const float*)d_in[12];
    const float* m2     = (const float*)d_in[13];
    const float* v2     = (const float*)d_in[14];

    float *A, *W1p, *H1, *H2;
    cudaGetSymbolAddress((void**)&A,   g_A);
    cudaGetSymbolAddress((void**)&W1p, g_W1p);
    cudaGetSymbolAddress((void**)&H1,  g_H1);
    cudaGetSymbolAddress((void**)&H2,  g_H2);

    // 1) permute w1 to [O][bin*256+c]
    permute_w1_kernel<<<25088, 256>>>(w1);

    // 2) roi-align im2col -> A
    roi_im2col_kernel<<<4096, 256>>>(images, kfi, boxes);

    // 3) FC1: [4096,512] = A[4096,12544] * W1p^T, + bias/BN/ReLU
    dim3 gdim(4096 / BM, 512 / BN);
    gemm_bn_relu_kernel<<<gdim, 256>>>(A, W1p, H1, 12544, b1, g1, bt1, m1, v1);

    // 4) FC2: [4096,512] = H1 * w2^T, + bias/BN/ReLU
    gemm_bn_relu_kernel<<<gdim, 256>>>(H1, w2, H2, 512, b2, g2, bt2, m2, v2);

    // 5) max over 8 keyframes
    max_k_kernel<<<512, 512>>>(H2, (float*)d_out);
}

// round 4
// speedup vs baseline: 2.6493x; 2.6493x over previous
#include <cuda_runtime.h>
#include <stdint.h>
#include <math.h>

#define EPSF 1e-3f

// ---------------- scratch (allocation-free: __device__ globals) ----------------
__device__ __align__(1024) float g_A  [4096UL * 12544UL];   // im2col  [R][bin*256+c], tf32-rounded
__device__ __align__(1024) float g_W1p[ 512UL * 12544UL];   // w1 perm [O][bin*256+c], tf32-rounded
__device__ __align__(1024) float g_W2r[ 512UL *   512UL];   // tf32-rounded w2
__device__ __align__(1024) float g_H1 [4096UL *   512UL];   // tf32-rounded FC1 out
__device__ __align__(1024) float g_H2 [4096UL *   512UL];

__device__ __forceinline__ float tf32r(float x) {
    uint32_t u;
    asm("cvt.rna.tf32.f32 %0, %1;" : "=r"(u) : "f"(x));
    return __uint_as_float(u);
}

// ------------------------------------------------------------------
// Permute + tf32-round w1 [O=512, C=256, 49] -> [O][bin*256+c]
// ------------------------------------------------------------------
__global__ void permute_w1_kernel(const float* __restrict__ w1) {
    __shared__ float buf[128 * 49];
    const int o  = blockIdx.x >> 1;
    const int c0 = (blockIdx.x & 1) * 128;
    const float* src = w1 + (size_t)o * 12544 + (size_t)c0 * 49;
    for (int i = threadIdx.x; i < 128 * 49; i += 256) buf[i] = src[i];
    __syncthreads();
    float* dst = g_W1p + (size_t)o * 12544;
    for (int i = threadIdx.x; i < 128 * 49; i += 256) {
        const int bin = i >> 7;
        const int cc  = i & 127;
        dst[bin * 256 + c0 + cc] = tf32r(buf[cc * 49 + bin]);
    }
}

__global__ void round_w2_kernel(const float* __restrict__ w2) {
    const int i = blockIdx.x * 256 + threadIdx.x;
    g_W2r[i] = tf32r(w2[i]);
}

// ------------------------------------------------------------------
// RoIAlign + im2col (tf32-rounded). Block=roi, thread=channel.
// ------------------------------------------------------------------
__global__ void roi_im2col_kernel(const float* __restrict__ images,
                                  const int*   __restrict__ kfi,
                                  const float* __restrict__ boxes) {
    const int r = blockIdx.x;
    const int c = threadIdx.x;

    const int f = kfi[r];
    const float x1 = boxes[r * 4 + 0] * 40.0f;
    const float y1 = boxes[r * 4 + 1] * 40.0f;
    const float x2 = boxes[r * 4 + 2] * 40.0f;
    const float y2 = boxes[r * 4 + 3] * 40.0f;
    const float bw = (x2 - x1) / 7.0f;
    const float bh = (y2 - y1) / 7.0f;

    const float* __restrict__ img = images + (size_t)f * 256 * 1600 + (size_t)c * 1600;
    float* __restrict__ arow = g_A + (size_t)r * 12544 + c;

    #pragma unroll 7
    for (int bin = 0; bin < 49; ++bin) {
        const int by = bin / 7;
        const int bx = bin - by * 7;
        const float X = x1 + ((float)bx + 0.5f) * bw;
        const float Y = y1 + ((float)by + 0.5f) * bh;
        const bool valid = (X > -1.0f) && (X < 40.0f) && (Y > -1.0f) && (Y < 40.0f);

        float x = fminf(fmaxf(X, 0.0f), 39.0f);
        float y = fminf(fmaxf(Y, 0.0f), 39.0f);
        const int x0 = (int)floorf(x);
        const int y0 = (int)floorf(y);
        const int x1i = min(x0 + 1, 39);
        const int y1i = min(y0 + 1, 39);
        const float lx = x - (float)x0;
        const float ly = y - (float)y0;

        float v = 0.0f;
        if (valid) {
            const float w00 = (1.0f - ly) * (1.0f - lx);
            const float w01 = (1.0f - ly) * lx;
            const float w10 = ly * (1.0f - lx);
            const float w11 = ly * lx;
            v = img[y0  * 40 + x0 ] * w00
              + img[y0  * 40 + x1i] * w01
              + img[y1i * 40 + x0 ] * w10
              + img[y1i * 40 + x1i] * w11;
        }
        arow[bin * 256] = tf32r(v);
    }
}

// ------------------------------------------------------------------
// tf32 mma.sync GEMM (base ISA, no 'a'-suffix features):
// C[M,512] = A[M,K] * B[512,K]^T  with fused bias + BN + ReLU.
// BM=BN=128, BK=32, 256 threads (8 warps, 2x4), warp tile 64x32.
// 3-stage cp.async pipeline, XOR-swizzled smem (conflict-free frags).
// ------------------------------------------------------------------
#define STAGES 3
#define STAGE_FLOATS 8192              // A 4096 + B 4096
#define GEMM_SMEM_BYTES (STAGES * STAGE_FLOATS * 4 + 1024)   // + BN scale/off

__device__ __forceinline__ void cpasync16(uint32_t s, const float* g) {
    asm volatile("cp.async.cg.shared.global [%0], [%1], 16;" :: "r"(s), "l"(g) : "memory");
}
__device__ __forceinline__ void mma_tf32(float* d, const uint32_t* a, const uint32_t* b) {
    asm volatile("mma.sync.aligned.m16n8k8.row.col.f32.tf32.tf32.f32 "
                 "{%0,%1,%2,%3}, {%4,%5,%6,%7}, {%8,%9}, {%0,%1,%2,%3};"
                 : "+f"(d[0]), "+f"(d[1]), "+f"(d[2]), "+f"(d[3])
                 : "r"(a[0]), "r"(a[1]), "r"(a[2]), "r"(a[3]), "r"(b[0]), "r"(b[1]));
}

__global__ __launch_bounds__(256) void gemm_mma_kernel(
    const float* __restrict__ A, const float* __restrict__ B,
    float* __restrict__ C, int K,
    const float* __restrict__ bias,
    const float* __restrict__ gamma, const float* __restrict__ beta,
    const float* __restrict__ mean,  const float* __restrict__ var,
    int round_out)
{
    extern __shared__ float smem[];
    float* sarr = smem + STAGES * STAGE_FLOATS;          // [128] BN scale
    float* oarr = sarr + 128;                            // [128] BN offset

    const int t    = threadIdx.x;
    const int lane = t & 31;
    const int wid  = t >> 5;
    const int mw   = wid & 1;          // 0..1
    const int nw   = wid >> 1;         // 0..3
    const int g    = lane >> 2;        // groupID
    const int tig  = lane & 3;         // thread in group
    const int bm   = blockIdx.x * 128;
    const int bn   = blockIdx.y * 128;

    // BN per-column scale/offset (before mainloop; separate smem region)
    for (int c2 = t; c2 < 128; c2 += 256) {
        const int cg = bn + c2;
        const float s = gamma[cg] * rsqrtf(var[cg] + EPSF);
        sarr[c2] = s;
        oarr[c2] = (bias[cg] - mean[cg]) * s + beta[cg];
    }

    // smem base (32-bit shared address)
    uint32_t sbase;
    asm("{ .reg .u64 t0; cvta.to.shared.u64 t0, %1; cvt.u32.u64 %0, t0; }"
        : "=r"(sbase) : "l"(smem));

    // per-thread cp.async source/dest precompute: 4 chunks for A, 4 for B
    const float* aG[4]; const float* bG[4];
    uint32_t aS[4], bS[4];
    #pragma unroll
    for (int j = 0; j < 4; ++j) {
        const int id = t + j * 256;       // 0..1023
        const int m  = id >> 3;           // row 0..127
        const int cc = id & 7;            // float4 chunk 0..7
        const uint32_t soff = (uint32_t)(m * 32 + ((cc ^ (m & 7)) << 2)) * 4;
        aG[j] = A + (size_t)(bm + m) * K + cc * 4;
        bG[j] = B + (size_t)(bn + m) * K + cc * 4;
        aS[j] = soff;
        bS[j] = soff + 4096 * 4;
    }

    const int nkt = K >> 5;   // k-tiles of 32

    // prefetch stages 0,1
    #pragma unroll
    for (int s = 0; s < 2; ++s) {
        const uint32_t stg = sbase + s * (STAGE_FLOATS * 4);
        #pragma unroll
        for (int j = 0; j < 4; ++j) {
            cpasync16(stg + aS[j], aG[j] + s * 32);
            cpasync16(stg + bS[j], bG[j] + s * 32);
        }
        asm volatile("cp.async.commit_group;" ::: "memory");
    }

    float acc[4][4][4];
    #pragma unroll
    for (int i = 0; i < 4; ++i)
        #pragma unroll
        for (int j = 0; j < 4; ++j)
            #pragma unroll
            for (int q = 0; q < 4; ++q) acc[i][j][q] = 0.0f;

    int st = 0;
    for (int kt = 0; kt < nkt; ++kt) {
        asm volatile("cp.async.wait_group 1;" ::: "memory");
        __syncthreads();

        // prefetch kt+2 into the stage just freed (prev iter's compute stage)
        const int kp = kt + 2;
        if (kp < nkt) {
            const int sp = (st + 2) % STAGES;
            const uint32_t stg = sbase + sp * (STAGE_FLOATS * 4);
            #pragma unroll
            for (int j = 0; j < 4; ++j) {
                cpasync16(stg + aS[j], aG[j] + kp * 32);
                cpasync16(stg + bS[j], bG[j] + kp * 32);
            }
        }
        asm volatile("cp.async.commit_group;" ::: "memory");

        const float* As = smem + st * STAGE_FLOATS;
        const float* Bs = As + 4096;

        #pragma unroll
        for (int kk = 0; kk < 4; ++kk) {
            uint32_t afr[4][4], bfr[4][2];
            #pragma unroll
            for (int mf = 0; mf < 4; ++mf) {
                const int r0 = mw * 64 + mf * 16 + g;
                const int c0 = ((kk * 2) ^ (r0 & 7)) << 2;
                const int c1 = ((kk * 2 + 1) ^ (r0 & 7)) << 2;
                afr[mf][0] = __float_as_uint(As[r0 * 32 + c0 + tig]);
                afr[mf][1] = __float_as_uint(As[(r0 + 8) * 32 + c0 + tig]);
                afr[mf][2] = __float_as_uint(As[r0 * 32 + c1 + tig]);
                afr[mf][3] = __float_as_uint(As[(r0 + 8) * 32 + c1 + tig]);
            }
            #pragma unroll
            for (int nf = 0; nf < 4; ++nf) {
                const int n0 = nw * 32 + nf * 8 + g;
                const int c0 = ((kk * 2) ^ (n0 & 7)) << 2;
                const int c1 = ((kk * 2 + 1) ^ (n0 & 7)) << 2;
                bfr[nf][0] = __float_as_uint(Bs[n0 * 32 + c0 + tig]);
                bfr[nf][1] = __float_as_uint(Bs[n0 * 32 + c1 + tig]);
            }
            #pragma unroll
            for (int mf = 0; mf < 4; ++mf)
                #pragma unroll
                for (int nf = 0; nf < 4; ++nf)
                    mma_tf32(acc[mf][nf], afr[mf], bfr[nf]);
        }
        st = (st + 1) % STAGES;
    }

    // epilogue: bias+BN+ReLU (+optional tf32 rounding), float2 stores
    #pragma unroll
    for (int mf = 0; mf < 4; ++mf) {
        const int r0 = bm + mw * 64 + mf * 16 + g;
        #pragma unroll
        for (int nf = 0; nf < 4; ++nf) {
            const int cl = nw * 32 + nf * 8 + tig * 2;   // local col
            const float s0 = sarr[cl],     s1 = sarr[cl + 1];
            const float o0 = oarr[cl],     o1 = oarr[cl + 1];
            float v00 = fmaxf(acc[mf][nf][0] * s0 + o0, 0.0f);
            float v01 = fmaxf(acc[mf][nf][1] * s1 + o1, 0.0f);
            float v10 = fmaxf(acc[mf][nf][2] * s0 + o0, 0.0f);
            float v11 = fmaxf(acc[mf][nf][3] * s1 + o1, 0.0f);
            if (round_out) {
                v00 = tf32r(v00); v01 = tf32r(v01);
                v10 = tf32r(v10); v11 = tf32r(v11);
            }
            *(float2*)(C + (size_t)r0 * 512 + bn + cl)       = make_float2(v00, v01);
            *(float2*)(C + (size_t)(r0 + 8) * 512 + bn + cl) = make_float2(v10, v11);
        }
    }
}

// ------------------------------------------------------------------
// max over K=8 keyframes
// ------------------------------------------------------------------
__global__ void max_k_kernel(const float* __restrict__ H2, float* __restrict__ out) {
    const int n = blockIdx.x;
    const int d = threadIdx.x;
    const float* p = H2 + (size_t)n * 8 * 512 + d;
    float m = p[0];
    #pragma unroll
    for (int k = 1; k < 8; ++k) m = fmaxf(m, p[(size_t)k * 512]);
    out[(size_t)n * 512 + d] = m;
}

// ------------------------------------------------------------------
extern "C" void kernel_launch(void* const* d_in, const int* in_sizes, int n_in,
                              void* d_out, int out_size) {
    const float* images = (const float*)d_in[0];
    const int*   kfi    = (const int*)  d_in[1];
    const float* boxes  = (const float*)d_in[2];
    const float* w1     = (const float*)d_in[3];
    const float* b1     = (const float*)d_in[4];
    const float* g1     = (const float*)d_in[5];
    const float* bt1    = (const float*)d_in[6];
    const float* m1     = (const float*)d_in[7];
    const float* v1     = (const float*)d_in[8];
    const float* w2     = (const float*)d_in[9];
    const float* b2     = (const float*)d_in[10];
    const float* g2     = (const float*)d_in[11];
    const float* bt2    = (const float*)d_in[12];
    const float* m2     = (const float*)d_in[13];
    const float* v2     = (const float*)d_in[14];

    float *A, *W1p, *W2r, *H1, *H2;
    cudaGetSymbolAddress((void**)&A,   g_A);
    cudaGetSymbolAddress((void**)&W1p, g_W1p);
    cudaGetSymbolAddress((void**)&W2r, g_W2r);
    cudaGetSymbolAddress((void**)&H1,  g_H1);
    cudaGetSymbolAddress((void**)&H2,  g_H2);

    cudaFuncSetAttribute(gemm_mma_kernel, cudaFuncAttributeMaxDynamicSharedMemorySize,
                         GEMM_SMEM_BYTES);

    // prep
    permute_w1_kernel<<<1024, 256>>>(w1);
    round_w2_kernel<<<1024, 256>>>(w2);
    roi_im2col_kernel<<<4096, 256>>>(images, kfi, boxes);

    // FC1: [4096,512] = A[4096,12544] x W1p^T  (+BN/ReLU, tf32-round output)
    gemm_mma_kernel<<<dim3(32, 4), 256, GEMM_SMEM_BYTES>>>(A, W1p, H1, 12544,
                                                           b1, g1, bt1, m1, v1, 1);
    // FC2: [4096,512] = H1 x W2r^T  (+BN/ReLU)
    gemm_mma_kernel<<<dim3(32, 4), 256, GEMM_SMEM_BYTES>>>(H1, W2r, H2, 512,
                                                           b2, g2, bt2, m2, v2, 0);
    // max over 8 keyframes
    max_k_kernel<<<512, 512>>>(H2, (float*)d_out);
}

// round 7
// speedup vs baseline: 5.3675x; 2.0260x over previous
#include <cuda_runtime.h>
#include <stdint.h>
#include <math.h>

#define EPSF 1e-3f

// ---------------- scratch (allocation-free: __device__ globals) ----------------
__device__ __align__(1024) float g_imgT[64UL * 1600UL * 256UL];  // [F][H*W][C]
__device__ __align__(1024) float g_A  [4096UL * 12544UL];   // im2col  [R][bin*256+c], tf32-rounded
__device__ __align__(1024) float g_W1p[ 512UL * 12544UL];   // w1 perm [O][bin*256+c], tf32-rounded
__device__ __align__(1024) float g_W2r[ 512UL *   512UL];   // tf32-rounded w2
__device__ __align__(1024) float g_H1 [4096UL *   512UL];   // tf32-rounded FC1 out
__device__ __align__(1024) float g_H2 [4096UL *   512UL];

__device__ __forceinline__ float tf32r(float x) {
    uint32_t u;
    asm("cvt.rna.tf32.f32 %0, %1;" : "=r"(u) : "f"(x));
    return __uint_as_float(u);
}

// ------------------------------------------------------------------
// Transpose images [F,C,1600] -> [F,1600,C].  32x32 tiles, both sides
// coalesced.  grid = (50, 8, 64), block = (32, 8).
// ------------------------------------------------------------------
__global__ void transpose_img_kernel(const float* __restrict__ images) {
    __shared__ float tile[32][33];
    const int f   = blockIdx.z;
    const int hw0 = blockIdx.x * 32;
    const int c0  = blockIdx.y * 32;
    const float* src = images + (size_t)f * 256 * 1600;
    float*       dst = g_imgT + (size_t)f * 1600 * 256;

    #pragma unroll
    for (int i = 0; i < 4; ++i) {
        const int c = c0 + threadIdx.y + i * 8;
        tile[threadIdx.y + i * 8][threadIdx.x] = src[(size_t)c * 1600 + hw0 + threadIdx.x];
    }
    __syncthreads();
    #pragma unroll
    for (int i = 0; i < 4; ++i) {
        const int hw = hw0 + threadIdx.y + i * 8;
        dst[(size_t)hw * 256 + c0 + threadIdx.x] = tile[threadIdx.x][threadIdx.y + i * 8];
    }
}

// ------------------------------------------------------------------
// Permute + tf32-round w1 [O=512, C=256, 49] -> [O][bin*256+c]
// ------------------------------------------------------------------
__global__ void permute_w1_kernel(const float* __restrict__ w1) {
    __shared__ float buf[128 * 49];
    const int o  = blockIdx.x >> 1;
    const int c0 = (blockIdx.x & 1) * 128;
    const float* src = w1 + (size_t)o * 12544 + (size_t)c0 * 49;
    for (int i = threadIdx.x; i < 128 * 49; i += 256) buf[i] = src[i];
    __syncthreads();
    float* dst = g_W1p + (size_t)o * 12544;
    for (int i = threadIdx.x; i < 128 * 49; i += 256) {
        const int bin = i >> 7;
        const int cc  = i & 127;
        dst[bin * 256 + c0 + cc] = tf32r(buf[cc * 49 + bin]);
    }
}

__global__ void round_w2_kernel(const float* __restrict__ w2) {
    const int i = blockIdx.x * 256 + threadIdx.x;
    g_W2r[i] = tf32r(w2[i]);
}

// ------------------------------------------------------------------
// RoIAlign + im2col from channel-last imgT.  Block=roi, thread=channel.
// All 4 taps per bin are fully-coalesced 1024B warp-group loads.
// ------------------------------------------------------------------
__global__ void roi_im2col_kernel(const int*   __restrict__ kfi,
                                  const float* __restrict__ boxes) {
    const int r = blockIdx.x;
    const int c = threadIdx.x;

    const int f = kfi[r];
    const float x1 = boxes[r * 4 + 0] * 40.0f;
    const float y1 = boxes[r * 4 + 1] * 40.0f;
    const float x2 = boxes[r * 4 + 2] * 40.0f;
    const float y2 = boxes[r * 4 + 3] * 40.0f;
    const float bw = (x2 - x1) / 7.0f;
    const float bh = (y2 - y1) / 7.0f;

    const float* __restrict__ img = g_imgT + (size_t)f * 1600 * 256;
    float* __restrict__ arow = g_A + (size_t)r * 12544 + c;

    #pragma unroll 7
    for (int bin = 0; bin < 49; ++bin) {
        const int by = bin / 7;
        const int bx = bin - by * 7;
        const float X = x1 + ((float)bx + 0.5f) * bw;
        const float Y = y1 + ((float)by + 0.5f) * bh;
        const bool valid = (X > -1.0f) && (X < 40.0f) && (Y > -1.0f) && (Y < 40.0f);

        float x = fminf(fmaxf(X, 0.0f), 39.0f);
        float y = fminf(fmaxf(Y, 0.0f), 39.0f);
        const int x0 = (int)floorf(x);
        const int y0 = (int)floorf(y);
        const int x1i = min(x0 + 1, 39);
        const int y1i = min(y0 + 1, 39);
        const float lx = x - (float)x0;
        const float ly = y - (float)y0;

        float v = 0.0f;
        if (valid) {
            const float w00 = (1.0f - ly) * (1.0f - lx);
            const float w01 = (1.0f - ly) * lx;
            const float w10 = ly * (1.0f - lx);
            const float w11 = ly * lx;
            const float* p00 = img + (size_t)(y0  * 40 + x0 ) * 256 + c;
            const float* p01 = img + (size_t)(y0  * 40 + x1i) * 256 + c;
            const float* p10 = img + (size_t)(y1i * 40 + x0 ) * 256 + c;
            const float* p11 = img + (size_t)(y1i * 40 + x1i) * 256 + c;
            v = p00[0] * w00 + p01[0] * w01 + p10[0] * w10 + p11[0] * w11;
        }
        arow[bin * 256] = tf32r(v);
    }
}

// ------------------------------------------------------------------
// tf32 mma.sync GEMM: C[M,512] = A[M,K] * B[512,K]^T + bias/BN/ReLU.
// BM=BN=128, BK=32, 256 threads (8 warps, 2x4), warp tile 64x32.
// 3-stage cp.async pipeline, XOR-swizzled smem.
// ------------------------------------------------------------------
#define STAGES 3
#define STAGE_FLOATS 8192
#define GEMM_SMEM_BYTES (STAGES * STAGE_FLOATS * 4 + 1024)

__device__ __forceinline__ void cpasync16(uint32_t s, const float* g) {
    asm volatile("cp.async.cg.shared.global [%0], [%1], 16;" :: "r"(s), "l"(g) : "memory");
}
__device__ __forceinline__ void mma_tf32(float* d, const uint32_t* a, const uint32_t* b) {
    asm volatile("mma.sync.aligned.m16n8k8.row.col.f32.tf32.tf32.f32 "
                 "{%0,%1,%2,%3}, {%4,%5,%6,%7}, {%8,%9}, {%0,%1,%2,%3};"
                 : "+f"(d[0]), "+f"(d[1]), "+f"(d[2]), "+f"(d[3])
                 : "r"(a[0]), "r"(a[1]), "r"(a[2]), "r"(a[3]), "r"(b[0]), "r"(b[1]));
}

__global__ __launch_bounds__(256) void gemm_mma_kernel(
    const float* __restrict__ A, const float* __restrict__ B,
    float* __restrict__ C, int K,
    const float* __restrict__ bias,
    const float* __restrict__ gamma, const float* __restrict__ beta,
    const float* __restrict__ mean,  const float* __restrict__ var,
    int round_out)
{
    extern __shared__ float smem[];
    float* sarr = smem + STAGES * STAGE_FLOATS;
    float* oarr = sarr + 128;

    const int t    = threadIdx.x;
    const int lane = t & 31;
    const int wid  = t >> 5;
    const int mw   = wid & 1;
    const int nw   = wid >> 1;
    const int g    = lane >> 2;
    const int tig  = lane & 3;
    const int bm   = blockIdx.x * 128;
    const int bn   = blockIdx.y * 128;

    for (int c2 = t; c2 < 128; c2 += 256) {
        const int cg = bn + c2;
        const float s = gamma[cg] * rsqrtf(var[cg] + EPSF);
        sarr[c2] = s;
        oarr[c2] = (bias[cg] - mean[cg]) * s + beta[cg];
    }

    uint32_t sbase;
    asm("{ .reg .u64 t0; cvta.to.shared.u64 t0, %1; cvt.u32.u64 %0, t0; }"
        : "=r"(sbase) : "l"(smem));

    const float* aG[4]; const float* bG[4];
    uint32_t aS[4], bS[4];
    #pragma unroll
    for (int j = 0; j < 4; ++j) {
        const int id = t + j * 256;
        const int m  = id >> 3;
        const int cc = id & 7;
        const uint32_t soff = (uint32_t)(m * 32 + ((cc ^ (m & 7)) << 2)) * 4;
        aG[j] = A + (size_t)(bm + m) * K + cc * 4;
        bG[j] = B + (size_t)(bn + m) * K + cc * 4;
        aS[j] = soff;
        bS[j] = soff + 4096 * 4;
    }

    const int nkt = K >> 5;

    #pragma unroll
    for (int s = 0; s < 2; ++s) {
        const uint32_t stg = sbase + s * (STAGE_FLOATS * 4);
        #pragma unroll
        for (int j = 0; j < 4; ++j) {
            cpasync16(stg + aS[j], aG[j] + s * 32);
            cpasync16(stg + bS[j], bG[j] + s * 32);
        }
        asm volatile("cp.async.commit_group;" ::: "memory");
    }

    float acc[4][4][4];
    #pragma unroll
    for (int i = 0; i < 4; ++i)
        #pragma unroll
        for (int j = 0; j < 4; ++j)
            #pragma unroll
            for (int q = 0; q < 4; ++q) acc[i][j][q] = 0.0f;

    int st = 0;
    for (int kt = 0; kt < nkt; ++kt) {
        asm volatile("cp.async.wait_group 1;" ::: "memory");
        __syncthreads();

        const int kp = kt + 2;
        if (kp < nkt) {
            const int sp = (st + 2) % STAGES;
            const uint32_t stg = sbase + sp * (STAGE_FLOATS * 4);
            #pragma unroll
            for (int j = 0; j < 4; ++j) {
                cpasync16(stg + aS[j], aG[j] + kp * 32);
                cpasync16(stg + bS[j], bG[j] + kp * 32);
            }
        }
        asm volatile("cp.async.commit_group;" ::: "memory");

        const float* As = smem + st * STAGE_FLOATS;
        const float* Bs = As + 4096;

        #pragma unroll
        for (int kk = 0; kk < 4; ++kk) {
            uint32_t afr[4][4], bfr[4][2];
            #pragma unroll
            for (int mf = 0; mf < 4; ++mf) {
                const int r0 = mw * 64 + mf * 16 + g;
                const int c0 = ((kk * 2) ^ (r0 & 7)) << 2;
                const int c1 = ((kk * 2 + 1) ^ (r0 & 7)) << 2;
                afr[mf][0] = __float_as_uint(As[r0 * 32 + c0 + tig]);
                afr[mf][1] = __float_as_uint(As[(r0 + 8) * 32 + c0 + tig]);
                afr[mf][2] = __float_as_uint(As[r0 * 32 + c1 + tig]);
                afr[mf][3] = __float_as_uint(As[(r0 + 8) * 32 + c1 + tig]);
            }
            #pragma unroll
            for (int nf = 0; nf < 4; ++nf) {
                const int n0 = nw * 32 + nf * 8 + g;
                const int c0 = ((kk * 2) ^ (n0 & 7)) << 2;
                const int c1 = ((kk * 2 + 1) ^ (n0 & 7)) << 2;
                bfr[nf][0] = __float_as_uint(Bs[n0 * 32 + c0 + tig]);
                bfr[nf][1] = __float_as_uint(Bs[n0 * 32 + c1 + tig]);
            }
            #pragma unroll
            for (int mf = 0; mf < 4; ++mf)
                #pragma unroll
                for (int nf = 0; nf < 4; ++nf)
                    mma_tf32(acc[mf][nf], afr[mf], bfr[nf]);
        }
        st = (st + 1) % STAGES;
    }

    #pragma unroll
    for (int mf = 0; mf < 4; ++mf) {
        const int r0 = bm + mw * 64 + mf * 16 + g;
        #pragma unroll
        for (int nf = 0; nf < 4; ++nf) {
            const int cl = nw * 32 + nf * 8 + tig * 2;
            const float s0 = sarr[cl],     s1 = sarr[cl + 1];
            const float o0 = oarr[cl],     o1 = oarr[cl + 1];
            float v00 = fmaxf(acc[mf][nf][0] * s0 + o0, 0.0f);
            float v01 = fmaxf(acc[mf][nf][1] * s1 + o1, 0.0f);
            float v10 = fmaxf(acc[mf][nf][2] * s0 + o0, 0.0f);
            float v11 = fmaxf(acc[mf][nf][3] * s1 + o1, 0.0f);
            if (round_out) {
                v00 = tf32r(v00); v01 = tf32r(v01);
                v10 = tf32r(v10); v11 = tf32r(v11);
            }
            *(float2*)(C + (size_t)r0 * 512 + bn + cl)       = make_float2(v00, v01);
            *(float2*)(C + (size_t)(r0 + 8) * 512 + bn + cl) = make_float2(v10, v11);
        }
    }
}

// ------------------------------------------------------------------
// max over K=8 keyframes
// ------------------------------------------------------------------
__global__ void max_k_kernel(const float* __restrict__ H2, float* __restrict__ out) {
    const int n = blockIdx.x;
    const int d = threadIdx.x;
    const float* p = H2 + (size_t)n * 8 * 512 + d;
    float m = p[0];
    #pragma unroll
    for (int k = 1; k < 8; ++k) m = fmaxf(m, p[(size_t)k * 512]);
    out[(size_t)n * 512 + d] = m;
}

// ------------------------------------------------------------------
extern "C" void kernel_launch(void* const* d_in, const int* in_sizes, int n_in,
                              void* d_out, int out_size) {
    const float* images = (const float*)d_in[0];
    const int*   kfi    = (const int*)  d_in[1];
    const float* boxes  = (const float*)d_in[2];
    const float* w1     = (const float*)d_in[3];
    const float* b1     = (const float*)d_in[4];
    const float* g1     = (const float*)d_in[5];
    const float* bt1    = (const float*)d_in[6];
    const float* m1     = (const float*)d_in[7];
    const float* v1     = (const float*)d_in[8];
    const float* w2     = (const float*)d_in[9];
    const float* b2     = (const float*)d_in[10];
    const float* g2     = (const float*)d_in[11];
    const float* bt2    = (const float*)d_in[12];
    const float* m2     = (const float*)d_in[13];
    const float* v2     = (const float*)d_in[14];

    float *A, *W1p, *W2r, *H1, *H2;
    cudaGetSymbolAddress((void**)&A,   g_A);
    cudaGetSymbolAddress((void**)&W1p, g_W1p);
    cudaGetSymbolAddress((void**)&W2r, g_W2r);
    cudaGetSymbolAddress((void**)&H1,  g_H1);
    cudaGetSymbolAddress((void**)&H2,  g_H2);

    cudaFuncSetAttribute(gemm_mma_kernel, cudaFuncAttributeMaxDynamicSharedMemorySize,
                         GEMM_SMEM_BYTES);

    // prep (independent, cheap)
    transpose_img_kernel<<<dim3(50, 8, 64), dim3(32, 8)>>>(images);
    permute_w1_kernel<<<1024, 256>>>(w1);
    round_w2_kernel<<<1024, 256>>>(w2);

    // roi-align im2col from channel-last layout
    roi_im2col_kernel<<<4096, 256>>>(kfi, boxes);

    // FC1
    gemm_mma_kernel<<<dim3(32, 4), 256, GEMM_SMEM_BYTES>>>(A, W1p, H1, 12544,
                                                           b1, g1, bt1, m1, v1, 1);
    // FC2
    gemm_mma_kernel<<<dim3(32, 4), 256, GEMM_SMEM_BYTES>>>(H1, W2r, H2, 512,
                                                           b2, g2, bt2, m2, v2, 0);
    // max over 8 keyframes
    max_k_kernel<<<512, 512>>>(H2, (float*)d_out);
}

// round 9
// speedup vs baseline: 5.5947x; 1.0423x over previous
#include <cuda_runtime.h>
#include <stdint.h>
#include <math.h>

#define EPSF 1e-3f

// ---------------- scratch (allocation-free: __device__ globals) ----------------
__device__ __align__(1024) float g_imgT[64UL * 1600UL * 256UL];  // [F][H*W][C]
__device__ __align__(1024) float g_A  [4096UL * 12544UL];   // im2col  [R][bin*256+c], tf32-rounded
__device__ __align__(1024) float g_W1p[ 512UL * 12544UL];   // w1 perm [O][bin*256+c], tf32-rounded
__device__ __align__(1024) float g_W2r[ 512UL *   512UL];   // tf32-rounded w2
__device__ __align__(1024) float g_H1 [4096UL *   512UL];   // tf32-rounded FC1 out
__device__ __align__(1024) float g_H2 [4096UL *   512UL];

__device__ __forceinline__ float tf32r(float x) {
    uint32_t u;
    asm("cvt.rna.tf32.f32 %0, %1;" : "=r"(u) : "f"(x));
    return __uint_as_float(u);
}

// ------------------------------------------------------------------
// Transpose images [F,C,1600] -> [F,1600,C].
// ------------------------------------------------------------------
__global__ void transpose_img_kernel(const float* __restrict__ images) {
    __shared__ float tile[32][33];
    const int f   = blockIdx.z;
    const int hw0 = blockIdx.x * 32;
    const int c0  = blockIdx.y * 32;
    const float* src = images + (size_t)f * 256 * 1600;
    float*       dst = g_imgT + (size_t)f * 1600 * 256;

    #pragma unroll
    for (int i = 0; i < 4; ++i) {
        const int c = c0 + threadIdx.y + i * 8;
        tile[threadIdx.y + i * 8][threadIdx.x] = src[(size_t)c * 1600 + hw0 + threadIdx.x];
    }
    __syncthreads();
    #pragma unroll
    for (int i = 0; i < 4; ++i) {
        const int hw = hw0 + threadIdx.y + i * 8;
        dst[(size_t)hw * 256 + c0 + threadIdx.x] = tile[threadIdx.x][threadIdx.y + i * 8];
    }
}

// ------------------------------------------------------------------
// Permute + tf32-round w1 [O=512, C=256, 49] -> [O][bin*256+c]
// ------------------------------------------------------------------
__global__ void permute_w1_kernel(const float* __restrict__ w1) {
    __shared__ float buf[128 * 49];
    const int o  = blockIdx.x >> 1;
    const int c0 = (blockIdx.x & 1) * 128;
    const float* src = w1 + (size_t)o * 12544 + (size_t)c0 * 49;
    for (int i = threadIdx.x; i < 128 * 49; i += 256) buf[i] = src[i];
    __syncthreads();
    float* dst = g_W1p + (size_t)o * 12544;
    for (int i = threadIdx.x; i < 128 * 49; i += 256) {
        const int bin = i >> 7;
        const int cc  = i & 127;
        dst[bin * 256 + c0 + cc] = tf32r(buf[cc * 49 + bin]);
    }
}

__global__ void round_w2_kernel(const float* __restrict__ w2) {
    const int i = blockIdx.x * 256 + threadIdx.x;
    g_W2r[i] = tf32r(w2[i]);
}

// ------------------------------------------------------------------
// RoIAlign + im2col from channel-last imgT.  Block=roi, thread=channel.
// ------------------------------------------------------------------
__global__ void roi_im2col_kernel(const int*   __restrict__ kfi,
                                  const float* __restrict__ boxes) {
    const int r = blockIdx.x;
    const int c = threadIdx.x;

    const int f = kfi[r];
    const float x1 = boxes[r * 4 + 0] * 40.0f;
    const float y1 = boxes[r * 4 + 1] * 40.0f;
    const float x2 = boxes[r * 4 + 2] * 40.0f;
    const float y2 = boxes[r * 4 + 3] * 40.0f;
    const float bw = (x2 - x1) / 7.0f;
    const float bh = (y2 - y1) / 7.0f;

    const float* __restrict__ img = g_imgT + (size_t)f * 1600 * 256;
    float* __restrict__ arow = g_A + (size_t)r * 12544 + c;

    #pragma unroll 7
    for (int bin = 0; bin < 49; ++bin) {
        const int by = bin / 7;
        const int bx = bin - by * 7;
        const float X = x1 + ((float)bx + 0.5f) * bw;
        const float Y = y1 + ((float)by + 0.5f) * bh;
        const bool valid = (X > -1.0f) && (X < 40.0f) && (Y > -1.0f) && (Y < 40.0f);

        float x = fminf(fmaxf(X, 0.0f), 39.0f);
        float y = fminf(fmaxf(Y, 0.0f), 39.0f);
        const int x0 = (int)floorf(x);
        const int y0 = (int)floorf(y);
        const int x1i = min(x0 + 1, 39);
        const int y1i = min(y0 + 1, 39);
        const float lx = x - (float)x0;
        const float ly = y - (float)y0;

        float v = 0.0f;
        if (valid) {
            const float w00 = (1.0f - ly) * (1.0f - lx);
            const float w01 = (1.0f - ly) * lx;
            const float w10 = ly * (1.0f - lx);
            const float w11 = ly * lx;
            const float* p00 = img + (size_t)(y0  * 40 + x0 ) * 256 + c;
            const float* p01 = img + (size_t)(y0  * 40 + x1i) * 256 + c;
            const float* p10 = img + (size_t)(y1i * 40 + x0 ) * 256 + c;
            const float* p11 = img + (size_t)(y1i * 40 + x1i) * 256 + c;
            v = p00[0] * w00 + p01[0] * w01 + p10[0] * w10 + p11[0] * w11;
        }
        arow[bin * 256] = tf32r(v);
    }
}

// ------------------------------------------------------------------
// tf32 mma.sync GEMM v2: C[M,512] = A[M,K] * B[512,K]^T + bias/BN/ReLU.
// BM=BN=128, BK=32, 128 threads (4 warps, 2x2), warp tile 64x64.
// 4-stage cp.async pipeline, XOR-swizzled smem.
// Halves smem crossbar traffic vs 8-warp/64x32 (fragment reuse 2x).
// ------------------------------------------------------------------
#define STAGES 4
#define STAGE_FLOATS 8192
#define GEMM_SMEM_BYTES (STAGES * STAGE_FLOATS * 4 + 1024)   // 132 KB

__device__ __forceinline__ void cpasync16(uint32_t s, const float* g) {
    asm volatile("cp.async.cg.shared.global [%0], [%1], 16;" :: "r"(s), "l"(g) : "memory");
}
__device__ __forceinline__ void mma_tf32(float* d, const uint32_t* a, const uint32_t* b) {
    asm volatile("mma.sync.aligned.m16n8k8.row.col.f32.tf32.tf32.f32 "
                 "{%0,%1,%2,%3}, {%4,%5,%6,%7}, {%8,%9}, {%0,%1,%2,%3};"
                 : "+f"(d[0]), "+f"(d[1]), "+f"(d[2]), "+f"(d[3])
                 : "r"(a[0]), "r"(a[1]), "r"(a[2]), "r"(a[3]), "r"(b[0]), "r"(b[1]));
}

__global__ __launch_bounds__(128, 1) void gemm_mma_kernel(
    const float* __restrict__ A, const float* __restrict__ B,
    float* __restrict__ C, int K,
    const float* __restrict__ bias,
    const float* __restrict__ gamma, const float* __restrict__ beta,
    const float* __restrict__ mean,  const float* __restrict__ var,
    int round_out)
{
    extern __shared__ float smem[];
    float* sarr = smem + STAGES * STAGE_FLOATS;
    float* oarr = sarr + 128;

    const int t    = threadIdx.x;
    const int lane = t & 31;
    const int wid  = t >> 5;
    const int mw   = wid & 1;          // 0..1 (M)
    const int nw   = wid >> 1;         // 0..1 (N)
    const int g    = lane >> 2;
    const int tig  = lane & 3;
    const int bm   = blockIdx.x * 128;
    const int bn   = blockIdx.y * 128;

    for (int c2 = t; c2 < 128; c2 += 128) {
        const int cg = bn + c2;
        const float s = gamma[cg] * rsqrtf(var[cg] + EPSF);
        sarr[c2] = s;
        oarr[c2] = (bias[cg] - mean[cg]) * s + beta[cg];
    }

    uint32_t sbase;
    asm("{ .reg .u64 t0; cvta.to.shared.u64 t0, %1; cvt.u32.u64 %0, t0; }"
        : "=r"(sbase) : "l"(smem));

    // cp.async chunk plan: 2048 16B-chunks per stage (A 1024 + B 1024),
    // 128 threads x 8 A-chunks + 8 B-chunks
    const float* aG[8]; const float* bG[8];
    uint32_t aS[8], bS[8];
    #pragma unroll
    for (int j = 0; j < 8; ++j) {
        const int id = t + j * 128;       // 0..1023
        const int m  = id >> 3;           // row 0..127
        const int cc = id & 7;            // float4 chunk 0..7
        const uint32_t soff = (uint32_t)(m * 32 + ((cc ^ (m & 7)) << 2)) * 4;
        aG[j] = A + (size_t)(bm + m) * K + cc * 4;
        bG[j] = B + (size_t)(bn + m) * K + cc * 4;
        aS[j] = soff;
        bS[j] = soff + 4096 * 4;
    }

    const int nkt = K >> 5;

    // prefetch stages 0..2
    const int npre = nkt < 3 ? nkt : 3;
    for (int s = 0; s < npre; ++s) {
        const uint32_t stg = sbase + s * (STAGE_FLOATS * 4);
        #pragma unroll
        for (int j = 0; j < 8; ++j) {
            cpasync16(stg + aS[j], aG[j] + s * 32);
            cpasync16(stg + bS[j], bG[j] + s * 32);
        }
        asm volatile("cp.async.commit_group;" ::: "memory");
    }

    float acc[4][8][4];
    #pragma unroll
    for (int i = 0; i < 4; ++i)
        #pragma unroll
        for (int j = 0; j < 8; ++j)
            #pragma unroll
            for (int q = 0; q < 4; ++q) acc[i][j][q] = 0.0f;

    for (int kt = 0; kt < nkt; ++kt) {
        const int st = kt & (STAGES - 1);
        asm volatile("cp.async.wait_group 2;" ::: "memory");
        __syncthreads();

        // prefetch kt+3 into the stage read during iteration kt-1
        const int kp = kt + 3;
        if (kp < nkt) {
            const int sp = kp & (STAGES - 1);
            const uint32_t stg = sbase + sp * (STAGE_FLOATS * 4);
            #pragma unroll
            for (int j = 0; j < 8; ++j) {
                cpasync16(stg + aS[j], aG[j] + kp * 32);
                cpasync16(stg + bS[j], bG[j] + kp * 32);
            }
        }
        asm volatile("cp.async.commit_group;" ::: "memory");

        const float* As = smem + st * STAGE_FLOATS;
        const float* Bs = As + 4096;

        #pragma unroll
        for (int kk = 0; kk < 4; ++kk) {
            uint32_t afr[4][4], bfr[8][2];
            #pragma unroll
            for (int mf = 0; mf < 4; ++mf) {
                const int r0 = mw * 64 + mf * 16 + g;
                const int c0 = ((kk * 2) ^ (r0 & 7)) << 2;
                const int c1 = ((kk * 2 + 1) ^ (r0 & 7)) << 2;
                afr[mf][0] = __float_as_uint(As[r0 * 32 + c0 + tig]);
                afr[mf][1] = __float_as_uint(As[(r0 + 8) * 32 + c0 + tig]);
                afr[mf][2] = __float_as_uint(As[r0 * 32 + c1 + tig]);
                afr[mf][3] = __float_as_uint(As[(r0 + 8) * 32 + c1 + tig]);
            }
            #pragma unroll
            for (int nf = 0; nf < 8; ++nf) {
                const int n0 = nw * 64 + nf * 8 + g;
                const int c0 = ((kk * 2) ^ (n0 & 7)) << 2;
                const int c1 = ((kk * 2 + 1) ^ (n0 & 7)) << 2;
                bfr[nf][0] = __float_as_uint(Bs[n0 * 32 + c0 + tig]);
                bfr[nf][1] = __float_as_uint(Bs[n0 * 32 + c1 + tig]);
            }
            #pragma unroll
            for (int mf = 0; mf < 4; ++mf)
                #pragma unroll
                for (int nf = 0; nf < 8; ++nf)
                    mma_tf32(acc[mf][nf], afr[mf], bfr[nf]);
        }
    }

    // epilogue: bias+BN+ReLU (+optional tf32 rounding), float2 stores
    #pragma unroll
    for (int mf = 0; mf < 4; ++mf) {
        const int r0 = bm + mw * 64 + mf * 16 + g;
        #pragma unroll
        for (int nf = 0; nf < 8; ++nf) {
            const int cl = nw * 64 + nf * 8 + tig * 2;
            const float s0 = sarr[cl],     s1 = sarr[cl + 1];
            const float o0 = oarr[cl],     o1 = oarr[cl + 1];
            float v00 = fmaxf(acc[mf][nf][0] * s0 + o0, 0.0f);
            float v01 = fmaxf(acc[mf][nf][1] * s1 + o1, 0.0f);
            float v10 = fmaxf(acc[mf][nf][2] * s0 + o0, 0.0f);
            float v11 = fmaxf(acc[mf][nf][3] * s1 + o1, 0.0f);
            if (round_out) {
                v00 = tf32r(v00); v01 = tf32r(v01);
                v10 = tf32r(v10); v11 = tf32r(v11);
            }
            *(float2*)(C + (size_t)r0 * 512 + bn + cl)       = make_float2(v00, v01);
            *(float2*)(C + (size_t)(r0 + 8) * 512 + bn + cl) = make_float2(v10, v11);
        }
    }
}

// ------------------------------------------------------------------
// max over K=8 keyframes
// ------------------------------------------------------------------
__global__ void max_k_kernel(const float* __restrict__ H2, float* __restrict__ out) {
    const int n = blockIdx.x;
    const int d = threadIdx.x;
    const float* p = H2 + (size_t)n * 8 * 512 + d;
    float m = p[0];
    #pragma unroll
    for (int k = 1; k < 8; ++k) m = fmaxf(m, p[(size_t)k * 512]);
    out[(size_t)n * 512 + d] = m;
}

// ------------------------------------------------------------------
extern "C" void kernel_launch(void* const* d_in, const int* in_sizes, int n_in,
                              void* d_out, int out_size) {
    const float* images = (const float*)d_in[0];
    const int*   kfi    = (const int*)  d_in[1];
    const float* boxes  = (const float*)d_in[2];
    const float* w1     = (const float*)d_in[3];
    const float* b1     = (const float*)d_in[4];
    const float* g1     = (const float*)d_in[5];
    const float* bt1    = (const float*)d_in[6];
    const float* m1     = (const float*)d_in[7];
    const float* v1     = (const float*)d_in[8];
    const float* w2     = (const float*)d_in[9];
    const float* b2     = (const float*)d_in[10];
    const float* g2     = (const float*)d_in[11];
    const float* bt2    = (const float*)d_in[12];
    const float* m2     = (const float*)d_in[13];
    const float* v2     = (const float*)d_in[14];

    float *A, *W1p, *W2r, *H1, *H2;
    cudaGetSymbolAddress((void**)&A,   g_A);
    cudaGetSymbolAddress((void**)&W1p, g_W1p);
    cudaGetSymbolAddress((void**)&W2r, g_W2r);
    cudaGetSymbolAddress((void**)&H1,  g_H1);
    cudaGetSymbolAddress((void**)&H2,  g_H2);

    cudaFuncSetAttribute(gemm_mma_kernel, cudaFuncAttributeMaxDynamicSharedMemorySize,
                         GEMM_SMEM_BYTES);

    // prep (independent, cheap)
    transpose_img_kernel<<<dim3(50, 8, 64), dim3(32, 8)>>>(images);
    permute_w1_kernel<<<1024, 256>>>(w1);
    round_w2_kernel<<<1024, 256>>>(w2);

    // roi-align im2col from channel-last layout
    roi_im2col_kernel<<<4096, 256>>>(kfi, boxes);

    // FC1
    gemm_mma_kernel<<<dim3(32, 4), 128, GEMM_SMEM_BYTES>>>(A, W1p, H1, 12544,
                                                           b1, g1, bt1, m1, v1, 1);
    // FC2
    gemm_mma_kernel<<<dim3(32, 4), 128, GEMM_SMEM_BYTES>>>(H1, W2r, H2, 512,
                                                           b2, g2, bt2, m2, v2, 0);
    // max over 8 keyframes
    max_k_kernel<<<512, 512>>>(H2, (float*)d_out);
}

// round 12
// speedup vs baseline: 6.1472x; 1.0988x over previous
#include <cuda_runtime.h>
#include <stdint.h>
#include <math.h>

#define EPSF 1e-3f

// ---------------- scratch (allocation-free: __device__ globals) ----------------
__device__ __align__(1024) float g_imgT[64UL * 1600UL * 256UL];  // [F][H*W][C]
__device__ __align__(1024) float g_A  [4096UL * 12544UL];   // im2col  [R][bin*256+c], tf32-rounded
__device__ __align__(1024) float g_W1p[ 512UL * 12544UL];   // w1 perm [O][bin*256+c], tf32-rounded
__device__ __align__(1024) float g_W2r[ 512UL *   512UL];   // tf32-rounded w2
__device__ __align__(1024) float g_H1 [4096UL *   512UL];   // tf32-rounded FC1 out
__device__ __align__(1024) float g_H2 [4096UL *   512UL];

__device__ __forceinline__ float tf32r(float x) {
    uint32_t u;
    asm("cvt.rna.tf32.f32 %0, %1;" : "=r"(u) : "f"(x));
    return __uint_as_float(u);
}

// ------------------------------------------------------------------
// Transpose images [F,C,1600] -> [F,1600,C].
// ------------------------------------------------------------------
__global__ void transpose_img_kernel(const float* __restrict__ images) {
    __shared__ float tile[32][33];
    const int f   = blockIdx.z;
    const int hw0 = blockIdx.x * 32;
    const int c0  = blockIdx.y * 32;
    const float* src = images + (size_t)f * 256 * 1600;
    float*       dst = g_imgT + (size_t)f * 1600 * 256;

    #pragma unroll
    for (int i = 0; i < 4; ++i) {
        const int c = c0 + threadIdx.y + i * 8;
        tile[threadIdx.y + i * 8][threadIdx.x] = src[(size_t)c * 1600 + hw0 + threadIdx.x];
    }
    __syncthreads();
    #pragma unroll
    for (int i = 0; i < 4; ++i) {
        const int hw = hw0 + threadIdx.y + i * 8;
        dst[(size_t)hw * 256 + c0 + threadIdx.x] = tile[threadIdx.x][threadIdx.y + i * 8];
    }
}

// ------------------------------------------------------------------
// Permute + tf32-round w1 [O=512, C=256, 49] -> [O][bin*256+c]
// ------------------------------------------------------------------
__global__ void permute_w1_kernel(const float* __restrict__ w1) {
    __shared__ float buf[128 * 49];
    const int o  = blockIdx.x >> 1;
    const int c0 = (blockIdx.x & 1) * 128;
    const float* src = w1 + (size_t)o * 12544 + (size_t)c0 * 49;
    for (int i = threadIdx.x; i < 128 * 49; i += 256) buf[i] = src[i];
    __syncthreads();
    float* dst = g_W1p + (size_t)o * 12544;
    for (int i = threadIdx.x; i < 128 * 49; i += 256) {
        const int bin = i >> 7;
        const int cc  = i & 127;
        dst[bin * 256 + c0 + cc] = tf32r(buf[cc * 49 + bin]);
    }
}

__global__ void round_w2_kernel(const float* __restrict__ w2) {
    const int i = blockIdx.x * 256 + threadIdx.x;
    g_W2r[i] = tf32r(w2[i]);
}

// ------------------------------------------------------------------
// RoIAlign + im2col, 2 channels per thread (float2), 128 thr/block.
// ------------------------------------------------------------------
__global__ __launch_bounds__(128) void roi_im2col_kernel(const int*   __restrict__ kfi,
                                                         const float* __restrict__ boxes) {
    const int r  = blockIdx.x;
    const int c2 = threadIdx.x;          // channel pair 0..127

    const int f = kfi[r];
    const float x1 = boxes[r * 4 + 0] * 40.0f;
    const float y1 = boxes[r * 4 + 1] * 40.0f;
    const float x2 = boxes[r * 4 + 2] * 40.0f;
    const float y2 = boxes[r * 4 + 3] * 40.0f;
    const float bw = (x2 - x1) / 7.0f;
    const float bh = (y2 - y1) / 7.0f;

    const float2* __restrict__ img =
        (const float2*)(g_imgT + (size_t)f * 1600 * 256) + c2;
    float2* __restrict__ arow = (float2*)(g_A + (size_t)r * 12544) + c2;

    #pragma unroll 7
    for (int bin = 0; bin < 49; ++bin) {
        const int by = bin / 7;
        const int bx = bin - by * 7;
        const float X = x1 + ((float)bx + 0.5f) * bw;
        const float Y = y1 + ((float)by + 0.5f) * bh;
        const bool valid = (X > -1.0f) && (X < 40.0f) && (Y > -1.0f) && (Y < 40.0f);

        float x = fminf(fmaxf(X, 0.0f), 39.0f);
        float y = fminf(fmaxf(Y, 0.0f), 39.0f);
        const int x0 = (int)floorf(x);
        const int y0 = (int)floorf(y);
        const int x1i = min(x0 + 1, 39);
        const int y1i = min(y0 + 1, 39);
        const float lx = x - (float)x0;
        const float ly = y - (float)y0;

        float2 v = make_float2(0.0f, 0.0f);
        if (valid) {
            const float w00 = (1.0f - ly) * (1.0f - lx);
            const float w01 = (1.0f - ly) * lx;
            const float w10 = ly * (1.0f - lx);
            const float w11 = ly * lx;
            const float2 p00 = img[(size_t)(y0  * 40 + x0 ) * 128];
            const float2 p01 = img[(size_t)(y0  * 40 + x1i) * 128];
            const float2 p10 = img[(size_t)(y1i * 40 + x0 ) * 128];
            const float2 p11 = img[(size_t)(y1i * 40 + x1i) * 128];
            v.x = p00.x * w00 + p01.x * w01 + p10.x * w10 + p11.x * w11;
            v.y = p00.y * w00 + p01.y * w01 + p10.y * w10 + p11.y * w11;
        }
        arow[bin * 128] = make_float2(tf32r(v.x), tf32r(v.y));
    }
}

// ------------------------------------------------------------------
// tf32 mma.sync GEMM v3: ldmatrix fragment loads.
// BM=BN=128, BK=32, 128 threads (4 warps, 2x2), warp tile 64x64.
// 4-stage cp.async pipeline, XOR-swizzled smem, LDSM.x4 frags.
// ------------------------------------------------------------------
#define STAGES 4
#define STAGE_FLOATS 8192
#define GEMM_SMEM_BYTES (STAGES * STAGE_FLOATS * 4 + 1024)   // 132 KB

__device__ __forceinline__ void cpasync16(uint32_t s, const float* g) {
    asm volatile("cp.async.cg.shared.global [%0], [%1], 16;" :: "r"(s), "l"(g) : "memory");
}
__device__ __forceinline__ void mma_tf32(float* d, const uint32_t* a, const uint32_t* b) {
    asm volatile("mma.sync.aligned.m16n8k8.row.col.f32.tf32.tf32.f32 "
                 "{%0,%1,%2,%3}, {%4,%5,%6,%7}, {%8,%9}, {%0,%1,%2,%3};"
                 : "+f"(d[0]), "+f"(d[1]), "+f"(d[2]), "+f"(d[3])
                 : "r"(a[0]), "r"(a[1]), "r"(a[2]), "r"(a[3]), "r"(b[0]), "r"(b[1]));
}
__device__ __forceinline__ void ldsm_x4(uint32_t* d, uint32_t addr) {
    asm volatile("ldmatrix.sync.aligned.m8n8.x4.shared.b16 {%0,%1,%2,%3}, [%4];"
                 : "=r"(d[0]), "=r"(d[1]), "=r"(d[2]), "=r"(d[3]) : "r"(addr));
}

__global__ __launch_bounds__(128, 1) void gemm_mma_kernel(
    const float* __restrict__ A, const float* __restrict__ B,
    float* __restrict__ C, int K,
    const float* __restrict__ bias,
    const float* __restrict__ gamma, const float* __restrict__ beta,
    const float* __restrict__ mean,  const float* __restrict__ var,
    int round_out)
{
    extern __shared__ float smem[];
    float* sarr = smem + STAGES * STAGE_FLOATS;
    float* oarr = sarr + 128;

    const int t    = threadIdx.x;
    const int lane = t & 31;
    const int wid  = t >> 5;
    const int mw   = wid & 1;          // 0..1 (M)
    const int nw   = wid >> 1;         // 0..1 (N)
    const int g    = lane >> 2;
    const int tig  = lane & 3;
    const int bm   = blockIdx.x * 128;
    const int bn   = blockIdx.y * 128;

    for (int c2 = t; c2 < 128; c2 += 128) {
        const int cg = bn + c2;
        const float s = gamma[cg] * rsqrtf(var[cg] + EPSF);
        sarr[c2] = s;
        oarr[c2] = (bias[cg] - mean[cg]) * s + beta[cg];
    }

    uint32_t sbase;
    asm("{ .reg .u64 t0; cvta.to.shared.u64 t0, %1; cvt.u32.u64 %0, t0; }"
        : "=r"(sbase) : "l"(smem));

    // ldmatrix per-lane addressing:
    //  A (x4): mat q = lane>>3 : row-half = q&1, k-chunk-half = q>>1
    //  B (x4): mat q = lane>>3 : k-chunk-half = q&1, n-row-half = q>>1
    const int rr   = lane & 7;
    const int rowa = mw * 64 + rr + ((lane >> 3) & 1) * 8;      // + mf*16
    const int qha  = (lane >> 4) & 1;
    const uint32_t aoff = (uint32_t)rowa * 128;
    const uint32_t swa  = (uint32_t)(rowa & 7);
    const int rowb = nw * 64 + rr + ((lane >> 4) & 1) * 8;      // + j*16
    const int qhb  = (lane >> 3) & 1;
    const uint32_t boff = (uint32_t)rowb * 128 + 4096 * 4;
    const uint32_t swb  = (uint32_t)(rowb & 7);

    // cp.async chunk plan: 2048 16B-chunks per stage (A 1024 + B 1024)
    const float* aG[8]; const float* bG[8];
    uint32_t aS[8], bS[8];
    #pragma unroll
    for (int j = 0; j < 8; ++j) {
        const int id = t + j * 128;       // 0..1023
        const int m  = id >> 3;           // row 0..127
        const int cc = id & 7;            // float4 chunk 0..7
        const uint32_t soff = (uint32_t)(m * 32 + ((cc ^ (m & 7)) << 2)) * 4;
        aG[j] = A + (size_t)(bm + m) * K + cc * 4;
        bG[j] = B + (size_t)(bn + m) * K + cc * 4;
        aS[j] = soff;
        bS[j] = soff + 4096 * 4;
    }

    const int nkt = K >> 5;

    const int npre = nkt < 3 ? nkt : 3;
    for (int s = 0; s < npre; ++s) {
        const uint32_t stg = sbase + s * (STAGE_FLOATS * 4);
        #pragma unroll
        for (int j = 0; j < 8; ++j) {
            cpasync16(stg + aS[j], aG[j] + s * 32);
            cpasync16(stg + bS[j], bG[j] + s * 32);
        }
        asm volatile("cp.async.commit_group;" ::: "memory");
    }

    float acc[4][8][4];
    #pragma unroll
    for (int i = 0; i < 4; ++i)
        #pragma unroll
        for (int j = 0; j < 8; ++j)
            #pragma unroll
            for (int q = 0; q < 4; ++q) acc[i][j][q] = 0.0f;

    for (int kt = 0; kt < nkt; ++kt) {
        const int st = kt & (STAGES - 1);
        asm volatile("cp.async.wait_group 2;" ::: "memory");
        __syncthreads();

        const int kp = kt + 3;
        if (kp < nkt) {
            const int sp = kp & (STAGES - 1);
            const uint32_t stg = sbase + sp * (STAGE_FLOATS * 4);
            #pragma unroll
            for (int j = 0; j < 8; ++j) {
                cpasync16(stg + aS[j], aG[j] + kp * 32);
                cpasync16(stg + bS[j], bG[j] + kp * 32);
            }
        }
        asm volatile("cp.async.commit_group;" ::: "memory");

        const uint32_t sAb = sbase + st * (STAGE_FLOATS * 4);

        #pragma unroll
        for (int kk = 0; kk < 4; ++kk) {
            uint32_t afr[4][4], bfr[8][2];
            const uint32_t ach = ((uint32_t)(2 * kk + qha) ^ swa) << 4;
            const uint32_t bch = ((uint32_t)(2 * kk + qhb) ^ swb) << 4;
            #pragma unroll
            for (int mf = 0; mf < 4; ++mf)
                ldsm_x4(afr[mf], sAb + aoff + (uint32_t)mf * 2048 + ach);
            #pragma unroll
            for (int j = 0; j < 4; ++j) {
                uint32_t d4[4];
                ldsm_x4(d4, sAb + boff + (uint32_t)j * 2048 + bch);
                bfr[2 * j][0]     = d4[0];
                bfr[2 * j][1]     = d4[1];
                bfr[2 * j + 1][0] = d4[2];
                bfr[2 * j + 1][1] = d4[3];
            }
            #pragma unroll
            for (int mf = 0; mf < 4; ++mf)
                #pragma unroll
                for (int nf = 0; nf < 8; ++nf)
                    mma_tf32(acc[mf][nf], afr[mf], bfr[nf]);
        }
    }

    // epilogue: bias+BN+ReLU (+optional tf32 rounding), float2 stores
    #pragma unroll
    for (int mf = 0; mf < 4; ++mf) {
        const int r0 = bm + mw * 64 + mf * 16 + g;
        #pragma unroll
        for (int nf = 0; nf < 8; ++nf) {
            const int cl = nw * 64 + nf * 8 + tig * 2;
            const float s0 = sarr[cl],     s1 = sarr[cl + 1];
            const float o0 = oarr[cl],     o1 = oarr[cl + 1];
            float v00 = fmaxf(acc[mf][nf][0] * s0 + o0, 0.0f);
            float v01 = fmaxf(acc[mf][nf][1] * s1 + o1, 0.0f);
            float v10 = fmaxf(acc[mf][nf][2] * s0 + o0, 0.0f);
            float v11 = fmaxf(acc[mf][nf][3] * s1 + o1, 0.0f);
            if (round_out) {
                v00 = tf32r(v00); v01 = tf32r(v01);
                v10 = tf32r(v10); v11 = tf32r(v11);
            }
            *(float2*)(C + (size_t)r0 * 512 + bn + cl)       = make_float2(v00, v01);
            *(float2*)(C + (size_t)(r0 + 8) * 512 + bn + cl) = make_float2(v10, v11);
        }
    }
}

// ------------------------------------------------------------------
// max over K=8 keyframes
// ------------------------------------------------------------------
__global__ void max_k_kernel(const float* __restrict__ H2, float* __restrict__ out) {
    const int n = blockIdx.x;
    const int d = threadIdx.x;
    const float* p = H2 + (size_t)n * 8 * 512 + d;
    float m = p[0];
    #pragma unroll
    for (int k = 1; k < 8; ++k) m = fmaxf(m, p[(size_t)k * 512]);
    out[(size_t)n * 512 + d] = m;
}

// ------------------------------------------------------------------
extern "C" void kernel_launch(void* const* d_in, const int* in_sizes, int n_in,
                              void* d_out, int out_size) {
    const float* images = (const float*)d_in[0];
    const int*   kfi    = (const int*)  d_in[1];
    const float* boxes  = (const float*)d_in[2];
    const float* w1     = (const float*)d_in[3];
    const float* b1     = (const float*)d_in[4];
    const float* g1     = (const float*)d_in[5];
    const float* bt1    = (const float*)d_in[6];
    const float* m1     = (const float*)d_in[7];
    const float* v1     = (const float*)d_in[8];
    const float* w2     = (const float*)d_in[9];
    const float* b2     = (const float*)d_in[10];
    const float* g2     = (const float*)d_in[11];
    const float* bt2    = (const float*)d_in[12];
    const float* m2     = (const float*)d_in[13];
    const float* v2     = (const float*)d_in[14];

    float *A, *W1p, *W2r, *H1, *H2;
    cudaGetSymbolAddress((void**)&A,   g_A);
    cudaGetSymbolAddress((void**)&W1p, g_W1p);
    cudaGetSymbolAddress((void**)&W2r, g_W2r);
    cudaGetSymbolAddress((void**)&H1,  g_H1);
    cudaGetSymbolAddress((void**)&H2,  g_H2);

    cudaFuncSetAttribute(gemm_mma_kernel, cudaFuncAttributeMaxDynamicSharedMemorySize,
                         GEMM_SMEM_BYTES);

    // prep (independent, cheap)
    transpose_img_kernel<<<dim3(50, 8, 64), dim3(32, 8)>>>(images);
    permute_w1_kernel<<<1024, 256>>>(w1);
    round_w2_kernel<<<1024, 256>>>(w2);

    // roi-align im2col from channel-last layout
    roi_im2col_kernel<<<4096, 128>>>(kfi, boxes);

    // FC1
    gemm_mma_kernel<<<dim3(32, 4), 128, GEMM_SMEM_BYTES>>>(A, W1p, H1, 12544,
                                                           b1, g1, bt1, m1, v1, 1);
    // FC2
    gemm_mma_kernel<<<dim3(32, 4), 128, GEMM_SMEM_BYTES>>>(H1, W2r, H2, 512,
                                                           b2, g2, bt2, m2, v2, 0);
    // max over 8 keyframes
    max_k_kernel<<<512, 512>>>(H2, (float*)d_out);
}